// round 2
// baseline (speedup 1.0000x reference)
#include <cuda_runtime.h>
#include <math.h>

#define BB       4096
#define SRC_LEN  128
#define IN_DIM   16
#define HH       64
#define SEQ_LEN  100
#define MEAN_DIM 4
#define COV_DIM  10

#define NG        4               // thread groups per CTA (64 threads each)
#define EPT       8               // batch elements per group
#define CTA_ELEMS (NG*EPT)        // 32
#define GRID1     (BB/CTA_ELEMS)  // 128
#define THREADS1  256

#define MEANS_OFF 0
#define COVS_OFF  (BB*SEQ_LEN*MEAN_DIM)   // 1638400

typedef unsigned long long ull;

// decoder output scratch [B][SEQ_LEN][IN_DIM]
__device__ __align__(16) float g_dec[BB*SEQ_LEN*IN_DIM];

// ---------------------------------------------------------------------------
// f32x2 packed helpers (Blackwell dual-fp32 FMA)
// ---------------------------------------------------------------------------
__device__ __forceinline__ ull pack2(float x, float y){
    ull r; asm("mov.b64 %0,{%1,%2};" : "=l"(r) : "f"(x), "f"(y)); return r;
}
__device__ __forceinline__ float2 unpack2(ull v){
    float2 r; asm("mov.b64 {%0,%1},%2;" : "=f"(r.x), "=f"(r.y) : "l"(v)); return r;
}
__device__ __forceinline__ ull fma2(ull a, ull b, ull c){
    ull d; asm("fma.rn.f32x2 %0,%1,%2,%3;" : "=l"(d) : "l"(a), "l"(b), "l"(c)); return d;
}

__device__ __forceinline__ float sigmoidf_(float x){
    return __fdividef(1.f, 1.f + __expf(-x));
}
__device__ __forceinline__ float tanhf_(float x){
    float u = __expf(-2.f * fabsf(x));
    float t = __fdividef(1.f - u, 1.f + u);
    return copysignf(t, x);
}

// ---------------------------------------------------------------------------
// SMEM layout for the sequential kernel  (~147 KB, dynamic)
// ---------------------------------------------------------------------------
struct SmemA {
    __align__(16) ull whh2[HH*192];            // Whh^T, duplicated lanes: [k][row] = (w,w)
    __align__(16) ull wih2[IN_DIM*192];        // Wih^T, duplicated lanes
    __align__(16) ull h2[NG][HH][EPT/2];       // h state: [g][k][e-pairs]
    __align__(16) ull xin2[NG][IN_DIM][EPT/2]; // current step input
    __align__(16) ull psum2[NG][4][IN_DIM][EPT/2]; // out-proj partials
    float bih[192], bhh[192];
    float outw[HH*IN_DIM];                     // out_W transposed [k][d]
    float outb[IN_DIM];
};

__device__ __forceinline__ float* h_rowf(SmemA& s, int g, int k){ return (float*)s.h2[g][k]; }
__device__ __forceinline__ float* xin_rowf(SmemA& s, int g, int d){ return (float*)s.xin2[g][d]; }
__device__ __forceinline__ float* psum_rowf(SmemA& s, int g, int ks, int d){ return (float*)s.psum2[g][ks][d]; }

__device__ __forceinline__ void load_gru_weights(SmemA& s,
        const float* __restrict__ Wih, const float* __restrict__ bih,
        const float* __restrict__ Whh, const float* __restrict__ bhh, int tid)
{
    for(int idx = tid; idx < HH*192; idx += THREADS1){
        int k = idx / 192, row = idx - k*192;
        float w = Whh[row*HH + k];
        s.whh2[idx] = pack2(w, w);
    }
    for(int idx = tid; idx < IN_DIM*192; idx += THREADS1){
        int k = idx / 192, row = idx - k*192;
        float w = Wih[row*IN_DIM + k];
        s.wih2[idx] = pack2(w, w);
    }
    for(int idx = tid; idx < 192; idx += THREADS1){
        s.bih[idx] = bih[idx];
        s.bhh[idx] = bhh[idx];
    }
}

// One GRU step for all NG*EPT elements. Thread (g,j) produces h[j] for its 8 elems.
// Contains 2 CTA barriers.
__device__ __forceinline__ void gru_step(SmemA& s, int g, int j)
{
    float br  = s.bih[j]      + s.bhh[j];
    float bz  = s.bih[64+j]   + s.bhh[64+j];
    float bni = s.bih[128+j];
    float bnh = s.bhh[128+j];

    ull ar0,ar1,ar2,ar3, az0,az1,az2,az3, an0,an1,an2,an3, ah0,ah1,ah2,ah3;
    ar0=ar1=ar2=ar3 = pack2(br, br);
    az0=az1=az2=az3 = pack2(bz, bz);
    an0=an1=an2=an3 = pack2(bni, bni);
    ah0=ah1=ah2=ah3 = pack2(bnh, bnh);

    // input contribution: gi = x @ Wih^T
    #pragma unroll
    for(int k = 0; k < IN_DIM; k++){
        const ulonglong2* xp = (const ulonglong2*)s.xin2[g][k];
        ulonglong2 xa = xp[0], xb = xp[1];
        const ull* w = &s.wih2[k*192];
        ull wr = w[j], wz = w[64+j], wn = w[128+j];
        ar0=fma2(xa.x,wr,ar0); ar1=fma2(xa.y,wr,ar1); ar2=fma2(xb.x,wr,ar2); ar3=fma2(xb.y,wr,ar3);
        az0=fma2(xa.x,wz,az0); az1=fma2(xa.y,wz,az1); az2=fma2(xb.x,wz,az2); az3=fma2(xb.y,wz,az3);
        an0=fma2(xa.x,wn,an0); an1=fma2(xa.y,wn,an1); an2=fma2(xb.x,wn,an2); an3=fma2(xb.y,wn,an3);
    }

    // recurrent contribution: gh = h @ Whh^T
    #pragma unroll 8
    for(int k = 0; k < HH; k++){
        const ulonglong2* hp = (const ulonglong2*)s.h2[g][k];
        ulonglong2 ha = hp[0], hb = hp[1];
        const ull* w = &s.whh2[k*192];
        ull wr = w[j], wz = w[64+j], wn = w[128+j];
        ar0=fma2(ha.x,wr,ar0); ar1=fma2(ha.y,wr,ar1); ar2=fma2(hb.x,wr,ar2); ar3=fma2(hb.y,wr,ar3);
        az0=fma2(ha.x,wz,az0); az1=fma2(ha.y,wz,az1); az2=fma2(hb.x,wz,az2); az3=fma2(hb.y,wz,az3);
        ah0=fma2(ha.x,wn,ah0); ah1=fma2(ha.y,wn,ah1); ah2=fma2(hb.x,wn,ah2); ah3=fma2(hb.y,wn,ah3);
    }

    float hold[EPT];
    {
        const float* hr = h_rowf(s, g, j);
        #pragma unroll
        for(int e = 0; e < EPT; e++) hold[e] = hr[e];
    }
    __syncthreads();   // all reads of h done before any write

    float rr[EPT], zz[EPT], ni[EPT], nh[EPT];
    { float2 t;
      t=unpack2(ar0); rr[0]=t.x; rr[1]=t.y;  t=unpack2(ar1); rr[2]=t.x; rr[3]=t.y;
      t=unpack2(ar2); rr[4]=t.x; rr[5]=t.y;  t=unpack2(ar3); rr[6]=t.x; rr[7]=t.y;
      t=unpack2(az0); zz[0]=t.x; zz[1]=t.y;  t=unpack2(az1); zz[2]=t.x; zz[3]=t.y;
      t=unpack2(az2); zz[4]=t.x; zz[5]=t.y;  t=unpack2(az3); zz[6]=t.x; zz[7]=t.y;
      t=unpack2(an0); ni[0]=t.x; ni[1]=t.y;  t=unpack2(an1); ni[2]=t.x; ni[3]=t.y;
      t=unpack2(an2); ni[4]=t.x; ni[5]=t.y;  t=unpack2(an3); ni[6]=t.x; ni[7]=t.y;
      t=unpack2(ah0); nh[0]=t.x; nh[1]=t.y;  t=unpack2(ah1); nh[2]=t.x; nh[3]=t.y;
      t=unpack2(ah2); nh[4]=t.x; nh[5]=t.y;  t=unpack2(ah3); nh[6]=t.x; nh[7]=t.y;
    }

    float* hw = h_rowf(s, g, j);
    #pragma unroll
    for(int e = 0; e < EPT; e++){
        float r = sigmoidf_(rr[e]);
        float z = sigmoidf_(zz[e]);
        float n = tanhf_(ni[e] + r * nh[e]);
        hw[e] = (1.f - z) * n + z * hold[e];
    }
    __syncthreads();   // writes visible before next consumer
}

// ---------------------------------------------------------------------------
// Kernel 1: encoder GRU (128 steps) + decoder GRU (100 steps, autoregressive)
// ---------------------------------------------------------------------------
__global__ void __launch_bounds__(THREADS1, 1) seq_kernel(
    const float* __restrict__ x,    const float* __restrict__ trg,
    const float* __restrict__ eWih, const float* __restrict__ ebih,
    const float* __restrict__ eWhh, const float* __restrict__ ebhh,
    const float* __restrict__ dWih, const float* __restrict__ dbih,
    const float* __restrict__ dWhh, const float* __restrict__ dbhh,
    const float* __restrict__ outW, const float* __restrict__ outb,
    const float* __restrict__ embW, const float* __restrict__ embb)
{
    extern __shared__ unsigned char smem_raw[];
    SmemA& s = *reinterpret_cast<SmemA*>(smem_raw);
    const int tid = threadIdx.x;
    const int g = tid >> 6;      // group 0..3
    const int j = tid & 63;      // h-row within group
    const int c = blockIdx.x;

    // ---- load encoder weights, zero h ----
    load_gru_weights(s, eWih, ebih, eWhh, ebhh, tid);
    for(int i = tid; i < NG*HH*EPT; i += THREADS1) ((float*)s.h2)[i] = 0.f;
    __syncthreads();

    // ---- encoder: 128 steps ----
    for(int t = 0; t < SRC_LEN; t++){
        for(int idx = tid; idx < NG*IN_DIM*EPT; idx += THREADS1){
            int gg = idx >> 7, r = idx & 127, e = r >> 4, d = r & 15;
            int b = c*CTA_ELEMS + gg*EPT + e;
            xin_rowf(s, gg, d)[e] = x[(b*SRC_LEN + t)*IN_DIM + d];
        }
        __syncthreads();
        gru_step(s, g, j);
    }

    // ---- switch to decoder weights ----
    load_gru_weights(s, dWih, dbih, dWhh, dbhh, tid);
    for(int idx = tid; idx < HH*IN_DIM; idx += THREADS1){
        int k = idx >> 4, d = idx & 15;
        s.outw[idx] = outW[d*HH + k];      // transposed [k][d]
    }
    if(tid < IN_DIM) s.outb[tid] = outb[tid];

    // ---- initial decoder input: emb(trg) ----
    for(int idx = tid; idx < NG*IN_DIM*EPT; idx += THREADS1){
        int gg = idx >> 7, r = idx & 127, e = r >> 4, d = r & 15;
        int b = c*CTA_ELEMS + gg*EPT + e;
        float a = embb[d];
        #pragma unroll
        for(int sx = 0; sx < 4; sx++) a += embW[d*4 + sx] * trg[b*4 + sx];
        xin_rowf(s, gg, d)[e] = a;
    }
    __syncthreads();

    // ---- decoder: 100 steps ----
    for(int t = 0; t < SEQ_LEN; t++){
        gru_step(s, g, j);

        // out projection partials: thread (d = j&15, ks = j>>4) covers 16 k's
        {
            int d = j & 15, ks = j >> 4;
            ull p0 = 0, p1 = 0, p2 = 0, p3 = 0;
            #pragma unroll
            for(int ki = 0; ki < 16; ki++){
                int k = ks*16 + ki;
                float w = s.outw[k*16 + d];
                ull wp = pack2(w, w);
                const ulonglong2* hp = (const ulonglong2*)s.h2[g][k];
                ulonglong2 ha = hp[0], hb = hp[1];
                p0 = fma2(ha.x, wp, p0); p1 = fma2(ha.y, wp, p1);
                p2 = fma2(hb.x, wp, p2); p3 = fma2(hb.y, wp, p3);
            }
            ull* pp = s.psum2[g][ks][d];
            pp[0] = p0; pp[1] = p1; pp[2] = p2; pp[3] = p3;
        }
        __syncthreads();

        // reduce partials -> o; feed back as next input; store dec_out
        if(j < IN_DIM){
            int d = j;
            #pragma unroll
            for(int e = 0; e < EPT; e++){
                float o = s.outb[d]
                        + psum_rowf(s, g, 0, d)[e] + psum_rowf(s, g, 1, d)[e]
                        + psum_rowf(s, g, 2, d)[e] + psum_rowf(s, g, 3, d)[e];
                xin_rowf(s, g, d)[e] = o;
                int b = c*CTA_ELEMS + g*EPT + e;
                g_dec[(b*SEQ_LEN + t)*IN_DIM + d] = o;
            }
        }
        __syncthreads();
    }
}

// ---------------------------------------------------------------------------
// Kernel 2: output heads (GELU-MLP x2), one (b,t) row per thread
// ---------------------------------------------------------------------------
__global__ void __launch_bounds__(256) heads_kernel(
    const float* __restrict__ mhW1, const float* __restrict__ mhb1,
    const float* __restrict__ mhW2, const float* __restrict__ mhb2,
    const float* __restrict__ chW1, const float* __restrict__ chb1,
    const float* __restrict__ chW2, const float* __restrict__ chb2,
    float* __restrict__ out)
{
    __shared__ float w1m[HH*IN_DIM], w1c[HH*IN_DIM];
    __shared__ float w2m[MEAN_DIM*HH], w2c[COV_DIM*HH];
    __shared__ float b1m[HH], b1c[HH], b2m[MEAN_DIM], b2c[COV_DIM];

    int tid = threadIdx.x;
    for(int i = tid; i < HH*IN_DIM; i += 256){ w1m[i] = mhW1[i]; w1c[i] = chW1[i]; }
    for(int i = tid; i < MEAN_DIM*HH; i += 256) w2m[i] = mhW2[i];
    for(int i = tid; i < COV_DIM*HH;  i += 256) w2c[i] = chW2[i];
    if(tid < HH){ b1m[tid] = mhb1[tid]; b1c[tid] = chb1[tid]; }
    if(tid < MEAN_DIM) b2m[tid] = mhb2[tid];
    if(tid < COV_DIM)  b2c[tid] = chb2[tid];
    __syncthreads();

    int row = blockIdx.x*256 + tid;      // 0 .. B*SEQ_LEN-1, grid sized exactly
    const float4* op = (const float4*)&g_dec[(size_t)row*IN_DIM];
    float4 o0 = op[0], o1 = op[1], o2 = op[2], o3 = op[3];
    float ov[16] = { o0.x,o0.y,o0.z,o0.w, o1.x,o1.y,o1.z,o1.w,
                     o2.x,o2.y,o2.z,o2.w, o3.x,o3.y,o3.z,o3.w };

    float am[MEAN_DIM], ac[COV_DIM];
    #pragma unroll
    for(int m = 0; m < MEAN_DIM; m++) am[m] = b2m[m];
    #pragma unroll
    for(int v = 0; v < COV_DIM; v++)  ac[v] = b2c[v];

    const float ISQRT2 = 0.70710678118654752f;
    #pragma unroll 4
    for(int u = 0; u < HH; u++){
        float s1 = b1m[u], s2 = b1c[u];
        #pragma unroll
        for(int d = 0; d < 16; d++){
            s1 += w1m[u*16 + d] * ov[d];
            s2 += w1c[u*16 + d] * ov[d];
        }
        float g1 = 0.5f * s1 * (1.f + erff(s1 * ISQRT2));
        float g2 = 0.5f * s2 * (1.f + erff(s2 * ISQRT2));
        #pragma unroll
        for(int m = 0; m < MEAN_DIM; m++) am[m] += g1 * w2m[m*HH + u];
        #pragma unroll
        for(int v = 0; v < COV_DIM; v++)  ac[v] += g2 * w2c[v*HH + u];
    }

    // clamp dims 2,3 of means to [-1, 1]
    am[2] = fminf(fmaxf(am[2], -1.f), 1.f);
    am[3] = fminf(fmaxf(am[3], -1.f), 1.f);

    #pragma unroll
    for(int m = 0; m < MEAN_DIM; m++) out[MEANS_OFF + (size_t)row*MEAN_DIM + m] = am[m];
    #pragma unroll
    for(int v = 0; v < COV_DIM; v++)  out[COVS_OFF + (size_t)row*COV_DIM + v] = ac[v];
}

// ---------------------------------------------------------------------------
extern "C" void kernel_launch(void* const* d_in, const int* in_sizes, int n_in,
                              void* d_out, int out_size)
{
    const float* x     = (const float*)d_in[0];
    const float* trg   = (const float*)d_in[1];
    const float* eWih  = (const float*)d_in[2];
    const float* ebih  = (const float*)d_in[3];
    const float* eWhh  = (const float*)d_in[4];
    const float* ebhh  = (const float*)d_in[5];
    const float* dWih  = (const float*)d_in[6];
    const float* dbih  = (const float*)d_in[7];
    const float* dWhh  = (const float*)d_in[8];
    const float* dbhh  = (const float*)d_in[9];
    const float* outW  = (const float*)d_in[10];
    const float* outb  = (const float*)d_in[11];
    const float* embW  = (const float*)d_in[12];
    const float* embb  = (const float*)d_in[13];
    const float* mhW1  = (const float*)d_in[14];
    const float* mhb1  = (const float*)d_in[15];
    const float* mhW2  = (const float*)d_in[16];
    const float* mhb2  = (const float*)d_in[17];
    const float* chW1  = (const float*)d_in[18];
    const float* chb1  = (const float*)d_in[19];
    const float* chW2  = (const float*)d_in[20];
    const float* chb2  = (const float*)d_in[21];

    cudaFuncSetAttribute(seq_kernel, cudaFuncAttributeMaxDynamicSharedMemorySize,
                         (int)sizeof(SmemA));

    seq_kernel<<<GRID1, THREADS1, sizeof(SmemA)>>>(
        x, trg, eWih, ebih, eWhh, ebhh, dWih, dbih, dWhh, dbhh,
        outW, outb, embW, embb);

    heads_kernel<<<(BB*SEQ_LEN)/256, 256>>>(
        mhW1, mhb1, mhW2, mhb2, chW1, chb1, chW2, chb2, (float*)d_out);
}

// round 3
// speedup vs baseline: 1.0475x; 1.0475x over previous
#include <cuda_runtime.h>
#include <math.h>

#define BB       4096
#define SRC_LEN  128
#define IN_DIM   16
#define HH       64
#define SEQ_LEN  100
#define MEAN_DIM 4
#define COV_DIM  10

#define THREADS1 128             // 4 warps per CTA, 1 per SMSP
#define GRID1    128             // 128 CTAs * 4 warps * 8 elems = 4096
#define MEANS_OFF 0
#define COVS_OFF  (BB*SEQ_LEN*MEAN_DIM)

typedef unsigned long long ull;

// decoder output scratch [B][SEQ_LEN][IN_DIM]
__device__ __align__(16) float g_dec[BB*SEQ_LEN*IN_DIM];

// ---------------------------------------------------------------------------
// f32x2 packed helpers
// ---------------------------------------------------------------------------
__device__ __forceinline__ ull pack2(float x, float y){
    ull r; asm("mov.b64 %0,{%1,%2};" : "=l"(r) : "f"(x), "f"(y)); return r;
}
__device__ __forceinline__ float2 unpack2(ull v){
    float2 r; asm("mov.b64 {%0,%1},%2;" : "=f"(r.x), "=f"(r.y) : "l"(v)); return r;
}
__device__ __forceinline__ ull fma2(ull a, ull b, ull c){
    ull d; asm("fma.rn.f32x2 %0,%1,%2,%3;" : "=l"(d) : "l"(a), "l"(b), "l"(c)); return d;
}

__device__ __forceinline__ float sigm(float x){
    float u = __expf(-x);
    return __fdividef(1.f, 1.f + u);
}
__device__ __forceinline__ float tanh_(float x){
    float u = __expf(-2.f * fabsf(x));
    float t = __fdividef(1.f - u, 1.f + u);
    return copysignf(t, x);
}

// ---------------------------------------------------------------------------
// SMEM (~74 KB dynamic)
// h layout per warp: hf[k*8 + e]  (k = h-row 0..63, e = elem 0..7)
// ull view: hv2[k*4 + p], p-th pair = elems (2p, 2p+1)
// x layout identical with k = d (0..15)
// ---------------------------------------------------------------------------
struct Smem {
    __align__(16) float wiT[IN_DIM*192];   // [k][gate*64 + j]
    __align__(16) float wT [HH*192];       // [k][gate*64 + j]
    __align__(16) float outwT[HH*IN_DIM];  // [k][d]
    __align__(16) ull   h2[4][HH*4];
    __align__(16) ull   x2[4][IN_DIM*4];
};

// ---------------------------------------------------------------------------
// Gate accumulation: rows (lane, lane+32). 24 fma2 per k.
// aN = n-gate accumulator (i-part or h-part depending on call).
// ---------------------------------------------------------------------------
template<int K>
__device__ __forceinline__ void gates_accum(
    const float* __restrict__ w, const ull* __restrict__ v, int lane,
    ull aR[2][4], ull aZ[2][4], ull aN[2][4])
{
    #pragma unroll 4
    for(int k = 0; k < K; k++){
        ulonglong2 v01 = *(const ulonglong2*)(v + k*4);
        ulonglong2 v23 = *(const ulonglong2*)(v + k*4 + 2);
        const float* wk = w + k*192;
        float wra = wk[lane],      wrb = wk[lane+32];
        float wza = wk[64+lane],   wzb = wk[96+lane];
        float wna = wk[128+lane],  wnb = wk[160+lane];
        ull ra = pack2(wra,wra), rb = pack2(wrb,wrb);
        ull za = pack2(wza,wza), zb = pack2(wzb,wzb);
        ull na = pack2(wna,wna), nb = pack2(wnb,wnb);
        aR[0][0]=fma2(v01.x,ra,aR[0][0]); aR[0][1]=fma2(v01.y,ra,aR[0][1]);
        aR[0][2]=fma2(v23.x,ra,aR[0][2]); aR[0][3]=fma2(v23.y,ra,aR[0][3]);
        aR[1][0]=fma2(v01.x,rb,aR[1][0]); aR[1][1]=fma2(v01.y,rb,aR[1][1]);
        aR[1][2]=fma2(v23.x,rb,aR[1][2]); aR[1][3]=fma2(v23.y,rb,aR[1][3]);
        aZ[0][0]=fma2(v01.x,za,aZ[0][0]); aZ[0][1]=fma2(v01.y,za,aZ[0][1]);
        aZ[0][2]=fma2(v23.x,za,aZ[0][2]); aZ[0][3]=fma2(v23.y,za,aZ[0][3]);
        aZ[1][0]=fma2(v01.x,zb,aZ[1][0]); aZ[1][1]=fma2(v01.y,zb,aZ[1][1]);
        aZ[1][2]=fma2(v23.x,zb,aZ[1][2]); aZ[1][3]=fma2(v23.y,zb,aZ[1][3]);
        aN[0][0]=fma2(v01.x,na,aN[0][0]); aN[0][1]=fma2(v01.y,na,aN[0][1]);
        aN[0][2]=fma2(v23.x,na,aN[0][2]); aN[0][3]=fma2(v23.y,na,aN[0][3]);
        aN[1][0]=fma2(v01.x,nb,aN[1][0]); aN[1][1]=fma2(v01.y,nb,aN[1][1]);
        aN[1][2]=fma2(v23.x,nb,aN[1][2]); aN[1][3]=fma2(v23.y,nb,aN[1][3]);
    }
}

// One full GRU step for this warp's 8 elements. 2 warp syncs.
__device__ __forceinline__ void gru_step(
    const float* __restrict__ wiT, const float* __restrict__ wT,
    ull* __restrict__ hv2, const ull* __restrict__ xv2, int lane,
    const ull br2[2], const ull bz2[2], const ull bni2[2], const ull bnh2[2])
{
    ull aR[2][4], aZ[2][4], aNi[2][4], aHn[2][4];
    #pragma unroll
    for(int rr = 0; rr < 2; rr++){
        #pragma unroll
        for(int p = 0; p < 4; p++){
            aR[rr][p]=br2[rr]; aZ[rr][p]=bz2[rr];
            aNi[rr][p]=bni2[rr]; aHn[rr][p]=bnh2[rr];
        }
    }
    gates_accum<IN_DIM>(wiT, xv2, lane, aR, aZ, aNi);
    gates_accum<HH>    (wT,  hv2, lane, aR, aZ, aHn);

    // read old h for own rows (vectorized)
    ulonglong2 old01[2], old23[2];
    #pragma unroll
    for(int rr = 0; rr < 2; rr++){
        int j = lane + rr*32;
        old01[rr] = *(const ulonglong2*)(hv2 + j*4);
        old23[rr] = *(const ulonglong2*)(hv2 + j*4 + 2);
    }
    __syncwarp();    // all gate reads of h complete

    #pragma unroll
    for(int rr = 0; rr < 2; rr++){
        int j = lane + rr*32;
        float hold[8];
        { float2 t;
          t=unpack2(old01[rr].x); hold[0]=t.x; hold[1]=t.y;
          t=unpack2(old01[rr].y); hold[2]=t.x; hold[3]=t.y;
          t=unpack2(old23[rr].x); hold[4]=t.x; hold[5]=t.y;
          t=unpack2(old23[rr].y); hold[6]=t.x; hold[7]=t.y; }
        float hn[8];
        #pragma unroll
        for(int p = 0; p < 4; p++){
            float2 r2  = unpack2(aR[rr][p]),  z2  = unpack2(aZ[rr][p]);
            float2 ni2 = unpack2(aNi[rr][p]), nh2 = unpack2(aHn[rr][p]);
            float r0 = sigm(r2.x), r1 = sigm(r2.y);
            float z0 = sigm(z2.x), z1 = sigm(z2.y);
            float n0 = tanh_(ni2.x + r0*nh2.x);
            float n1 = tanh_(ni2.y + r1*nh2.y);
            hn[2*p]   = (1.f - z0)*n0 + z0*hold[2*p];
            hn[2*p+1] = (1.f - z1)*n1 + z1*hold[2*p+1];
        }
        ulonglong2 s01, s23;
        s01.x = pack2(hn[0],hn[1]); s01.y = pack2(hn[2],hn[3]);
        s23.x = pack2(hn[4],hn[5]); s23.y = pack2(hn[6],hn[7]);
        *(ulonglong2*)(hv2 + j*4)     = s01;
        *(ulonglong2*)(hv2 + j*4 + 2) = s23;
    }
    __syncwarp();    // h writes visible
}

// ---------------------------------------------------------------------------
// Kernel 1: encoder (128 steps) + decoder (100 steps), warp-autonomous
// ---------------------------------------------------------------------------
__global__ void __launch_bounds__(THREADS1, 1) seq_kernel(
    const float* __restrict__ x,    const float* __restrict__ trg,
    const float* __restrict__ eWih, const float* __restrict__ ebih,
    const float* __restrict__ eWhh, const float* __restrict__ ebhh,
    const float* __restrict__ dWih, const float* __restrict__ dbih,
    const float* __restrict__ dWhh, const float* __restrict__ dbhh,
    const float* __restrict__ outW, const float* __restrict__ outb,
    const float* __restrict__ embW, const float* __restrict__ embb)
{
    extern __shared__ unsigned char smem_raw[];
    Smem& s = *reinterpret_cast<Smem*>(smem_raw);
    const int tid  = threadIdx.x;
    const int w    = tid >> 5;
    const int lane = tid & 31;
    const int warpB = (blockIdx.x*4 + w)*8;   // base batch index

    // ---- encoder weights (transposed) + out-proj weights ----
    for(int i = tid; i < HH*192; i += THREADS1){
        int k = i / 192, r = i - k*192;
        s.wT[i] = eWhh[r*HH + k];
    }
    for(int i = tid; i < IN_DIM*192; i += THREADS1){
        int k = i / 192, r = i - k*192;
        s.wiT[i] = eWih[r*IN_DIM + k];
    }
    for(int i = tid; i < HH*IN_DIM; i += THREADS1){
        int k = i >> 4, d = i & 15;
        s.outwT[i] = outW[d*HH + k];
    }
    __syncthreads();

    ull* hv2 = s.h2[w];
    ull* xv2 = s.x2[w];
    float* xf = (float*)xv2;

    // zero own h rows
    #pragma unroll
    for(int rr = 0; rr < 2; rr++){
        int j = lane + rr*32;
        ulonglong2 z; z.x = 0ull; z.y = 0ull;
        *(ulonglong2*)(hv2 + j*4)     = z;
        *(ulonglong2*)(hv2 + j*4 + 2) = z;
    }

    // packed encoder biases
    ull br2[2], bz2[2], bni2[2], bnh2[2];
    #pragma unroll
    for(int rr = 0; rr < 2; rr++){
        int j = lane + rr*32;
        float br = ebih[j] + ebhh[j];
        float bz = ebih[64+j] + ebhh[64+j];
        br2[rr]  = pack2(br, br);
        bz2[rr]  = pack2(bz, bz);
        bni2[rr] = pack2(ebih[128+j], ebih[128+j]);
        bnh2[rr] = pack2(ebhh[128+j], ebhh[128+j]);
    }

    // x gather mapping: lane -> (elem e, dims d0..d0+3)
    const int e  = lane >> 2;
    const int d0 = (lane & 3) * 4;
    const float* xbase = x + ((size_t)(warpB + e)*SRC_LEN)*IN_DIM + d0;
    float4 xv = *(const float4*)xbase;    // t = 0
    __syncwarp();                          // h zeros visible

    // ================= encoder =================
    for(int t = 0; t < SRC_LEN; t++){
        xf[(d0+0)*8 + e] = xv.x;
        xf[(d0+1)*8 + e] = xv.y;
        xf[(d0+2)*8 + e] = xv.z;
        xf[(d0+3)*8 + e] = xv.w;
        __syncwarp();
        if(t + 1 < SRC_LEN)
            xv = *(const float4*)(xbase + (size_t)(t+1)*IN_DIM);
        gru_step(s.wiT, s.wT, hv2, xv2, lane, br2, bz2, bni2, bnh2);
    }

    // ---- switch to decoder weights ----
    __syncthreads();
    for(int i = tid; i < HH*192; i += THREADS1){
        int k = i / 192, r = i - k*192;
        s.wT[i] = dWhh[r*HH + k];
    }
    for(int i = tid; i < IN_DIM*192; i += THREADS1){
        int k = i / 192, r = i - k*192;
        s.wiT[i] = dWih[r*IN_DIM + k];
    }
    __syncthreads();

    // decoder biases
    #pragma unroll
    for(int rr = 0; rr < 2; rr++){
        int j = lane + rr*32;
        float br = dbih[j] + dbhh[j];
        float bz = dbih[64+j] + dbhh[64+j];
        br2[rr]  = pack2(br, br);
        bz2[rr]  = pack2(bz, bz);
        bni2[rr] = pack2(dbih[128+j], dbih[128+j]);
        bnh2[rr] = pack2(dbhh[128+j], dbhh[128+j]);
    }

    // initial decoder input: emb(trg)
    {
        float4 tv = *(const float4*)(trg + (size_t)(warpB + e)*4);
        #pragma unroll
        for(int i = 0; i < 4; i++){
            int d = d0 + i;
            float a = embb[d] + embW[d*4+0]*tv.x + embW[d*4+1]*tv.y
                              + embW[d*4+2]*tv.z + embW[d*4+3]*tv.w;
            xf[d*8 + e] = a;
        }
    }
    const int dd  = lane >> 1;          // out dim 0..15
    const int pp0 = (lane & 1)*2;       // elem-pair base (0 or 2)
    const float ob = outb[dd];
    __syncwarp();

    // ================= decoder =================
    for(int t = 0; t < SEQ_LEN; t++){
        gru_step(s.wiT, s.wT, hv2, xv2, lane, br2, bz2, bni2, bnh2);

        // out projection: lane computes o[dd][e] for 4 elems
        ull o20 = pack2(ob, ob), o21 = pack2(ob, ob);
        #pragma unroll 8
        for(int k = 0; k < HH; k++){
            ulonglong2 hp = *(const ulonglong2*)(hv2 + k*4 + pp0);
            float wv = s.outwT[k*16 + dd];
            ull wp = pack2(wv, wv);
            o20 = fma2(hp.x, wp, o20);
            o21 = fma2(hp.y, wp, o21);
        }
        float2 oa = unpack2(o20), obp = unpack2(o21);
        int e0 = pp0*2;                 // 0 or 4
        xf[dd*8 + e0]     = oa.x;
        xf[dd*8 + e0 + 1] = oa.y;
        xf[dd*8 + e0 + 2] = obp.x;
        xf[dd*8 + e0 + 3] = obp.y;
        size_t gb = ((size_t)(warpB + e0)*SEQ_LEN + t)*IN_DIM + dd;
        const size_t ES = (size_t)SEQ_LEN*IN_DIM;
        g_dec[gb]        = oa.x;
        g_dec[gb + ES]   = oa.y;
        g_dec[gb + 2*ES] = obp.x;
        g_dec[gb + 3*ES] = obp.y;
        __syncwarp();
    }
}

// ---------------------------------------------------------------------------
// Kernel 2: output heads, f32x2 over d-pairs, one row per thread
// ---------------------------------------------------------------------------
__global__ void __launch_bounds__(256) heads_kernel(
    const float* __restrict__ mhW1, const float* __restrict__ mhb1,
    const float* __restrict__ mhW2, const float* __restrict__ mhb2,
    const float* __restrict__ chW1, const float* __restrict__ chb1,
    const float* __restrict__ chW2, const float* __restrict__ chb2,
    float* __restrict__ out)
{
    __shared__ __align__(16) float w1m[HH*IN_DIM], w1c[HH*IN_DIM];
    __shared__ __align__(16) ull  w2mP[HH*2];   // [u][mp] packed mean-pairs
    __shared__ __align__(16) ull  w2cP[HH*5];   // [u][vp] packed cov-pairs
    __shared__ float b1m[HH], b1c[HH];
    __shared__ float b2m[MEAN_DIM], b2c[COV_DIM];

    int tid = threadIdx.x;
    for(int i = tid; i < HH*IN_DIM; i += 256){ w1m[i] = mhW1[i]; w1c[i] = chW1[i]; }
    for(int i = tid; i < HH*2; i += 256){
        int u = i >> 1, mp = i & 1;
        w2mP[i] = pack2(mhW2[(2*mp)*HH + u], mhW2[(2*mp+1)*HH + u]);
    }
    for(int i = tid; i < HH*5; i += 256){
        int u = i / 5, vp = i - u*5;
        w2cP[i] = pack2(chW2[(2*vp)*HH + u], chW2[(2*vp+1)*HH + u]);
    }
    if(tid < HH){ b1m[tid] = mhb1[tid]; b1c[tid] = chb1[tid]; }
    if(tid < MEAN_DIM) b2m[tid] = mhb2[tid];
    if(tid < COV_DIM)  b2c[tid] = chb2[tid];
    __syncthreads();

    int row = blockIdx.x*256 + tid;
    // load row as 8 packed d-pairs
    const ulonglong2* op = (const ulonglong2*)&g_dec[(size_t)row*IN_DIM];
    ulonglong2 q0 = op[0], q1 = op[1], q2 = op[2], q3 = op[3];
    ull ov2[8] = { q0.x, q0.y, q1.x, q1.y, q2.x, q2.y, q3.x, q3.y };

    ull am2[2], ac2[5];
    am2[0] = pack2(b2m[0], b2m[1]);
    am2[1] = pack2(b2m[2], b2m[3]);
    #pragma unroll
    for(int vp = 0; vp < 5; vp++) ac2[vp] = pack2(b2c[2*vp], b2c[2*vp+1]);

    const float ISQRT2 = 0.70710678118654752f;
    #pragma unroll 4
    for(int u = 0; u < HH; u++){
        const ull* w1mp = (const ull*)(w1m + u*16);
        const ull* w1cp = (const ull*)(w1c + u*16);
        ull a1 = 0, a2 = 0;
        #pragma unroll
        for(int i = 0; i < 8; i++){
            a1 = fma2(ov2[i], w1mp[i], a1);
            a2 = fma2(ov2[i], w1cp[i], a2);
        }
        float2 f1 = unpack2(a1), f2 = unpack2(a2);
        float s1 = b1m[u] + f1.x + f1.y;
        float s2 = b1c[u] + f2.x + f2.y;
        float g1 = 0.5f * s1 * (1.f + erff(s1 * ISQRT2));
        float g2 = 0.5f * s2 * (1.f + erff(s2 * ISQRT2));
        ull g1p = pack2(g1, g1), g2p = pack2(g2, g2);
        am2[0] = fma2(g1p, w2mP[u*2],   am2[0]);
        am2[1] = fma2(g1p, w2mP[u*2+1], am2[1]);
        #pragma unroll
        for(int vp = 0; vp < 5; vp++)
            ac2[vp] = fma2(g2p, w2cP[u*5+vp], ac2[vp]);
    }

    // clamp means dims 2,3 to [-1,1]
    { float2 m23 = unpack2(am2[1]);
      m23.x = fminf(fmaxf(m23.x, -1.f), 1.f);
      m23.y = fminf(fmaxf(m23.y, -1.f), 1.f);
      am2[1] = pack2(m23.x, m23.y); }

    ull* om = (ull*)(out + MEANS_OFF) + (size_t)row*2;
    om[0] = am2[0]; om[1] = am2[1];
    ull* oc = (ull*)(out + COVS_OFF) + (size_t)row*5;
    #pragma unroll
    for(int vp = 0; vp < 5; vp++) oc[vp] = ac2[vp];
}

// ---------------------------------------------------------------------------
extern "C" void kernel_launch(void* const* d_in, const int* in_sizes, int n_in,
                              void* d_out, int out_size)
{
    const float* x     = (const float*)d_in[0];
    const float* trg   = (const float*)d_in[1];
    const float* eWih  = (const float*)d_in[2];
    const float* ebih  = (const float*)d_in[3];
    const float* eWhh  = (const float*)d_in[4];
    const float* ebhh  = (const float*)d_in[5];
    const float* dWih  = (const float*)d_in[6];
    const float* dbih  = (const float*)d_in[7];
    const float* dWhh  = (const float*)d_in[8];
    const float* dbhh  = (const float*)d_in[9];
    const float* outW  = (const float*)d_in[10];
    const float* outb  = (const float*)d_in[11];
    const float* embW  = (const float*)d_in[12];
    const float* embb  = (const float*)d_in[13];
    const float* mhW1  = (const float*)d_in[14];
    const float* mhb1  = (const float*)d_in[15];
    const float* mhW2  = (const float*)d_in[16];
    const float* mhb2  = (const float*)d_in[17];
    const float* chW1  = (const float*)d_in[18];
    const float* chb1  = (const float*)d_in[19];
    const float* chW2  = (const float*)d_in[20];
    const float* chb2  = (const float*)d_in[21];

    cudaFuncSetAttribute(seq_kernel, cudaFuncAttributeMaxDynamicSharedMemorySize,
                         (int)sizeof(Smem));

    seq_kernel<<<GRID1, THREADS1, sizeof(Smem)>>>(
        x, trg, eWih, ebih, eWhh, ebhh, dWih, dbih, dWhh, dbhh,
        outW, outb, embW, embb);

    heads_kernel<<<(BB*SEQ_LEN)/256, 256>>>(
        mhW1, mhb1, mhW2, mhb2, chW1, chb1, chW2, chb2, (float*)d_out);
}

// round 4
// speedup vs baseline: 1.3321x; 1.2717x over previous
#include <cuda_runtime.h>
#include <math.h>

#define BB       4096
#define SRC_LEN  128
#define IN_DIM   16
#define HH       64
#define SEQ_LEN  100
#define MEAN_DIM 4
#define COV_DIM  10

#define THREADS1 128             // 4 warps per CTA, 1 per SMSP
#define GRID1    128             // 128 CTAs * 4 warps * 8 elems = 4096
#define MEANS_OFF 0
#define COVS_OFF  (BB*SEQ_LEN*MEAN_DIM)

#define WSTRIDE   68             // padded row stride (floats) for Whh rows
#define WISTRIDE  20             // padded row stride for Wih rows
#define OWSTRIDE  68             // padded row stride for outW rows

typedef unsigned long long ull;

// decoder output scratch [B][SEQ_LEN][IN_DIM]
__device__ __align__(16) float g_dec[BB*SEQ_LEN*IN_DIM];

// ---------------------------------------------------------------------------
// f32x2 packed helpers
// ---------------------------------------------------------------------------
__device__ __forceinline__ ull pack2(float x, float y){
    ull r; asm("mov.b64 %0,{%1,%2};" : "=l"(r) : "f"(x), "f"(y)); return r;
}
__device__ __forceinline__ float2 unpack2(ull v){
    float2 r; asm("mov.b64 {%0,%1},%2;" : "=f"(r.x), "=f"(r.y) : "l"(v)); return r;
}
__device__ __forceinline__ ull fma2(ull a, ull b, ull c){
    ull d; asm("fma.rn.f32x2 %0,%1,%2,%3;" : "=l"(d) : "l"(a), "l"(b), "l"(c)); return d;
}
__device__ __forceinline__ float tanhapx(float x){
    float y; asm("tanh.approx.f32 %0,%1;" : "=f"(y) : "f"(x)); return y;
}
// sigmoid(x) = 0.5 + 0.5*tanh(0.5x)  (1 MUFU)
__device__ __forceinline__ float sigm(float x){
    return fmaf(tanhapx(0.5f*x), 0.5f, 0.5f);
}

// ---------------------------------------------------------------------------
// SMEM (~83 KB dynamic)
// ---------------------------------------------------------------------------
struct Smem {
    __align__(16) float wT [192*WSTRIDE];    // Whh rows, padded stride
    __align__(16) float wiT[192*WISTRIDE];   // Wih rows, padded stride
    __align__(16) float outw[16*OWSTRIDE];   // outW rows, padded stride
    __align__(16) ull   h2[4][HH*4];         // [warp][k*4 + pair]
    __align__(16) ull   x2[4][2][IN_DIM*4];  // [warp][buf][d*4 + pair]
};

// ---------------------------------------------------------------------------
// Gate accumulation, k-quad structured. Rows (lane, lane+32) per gate.
// ---------------------------------------------------------------------------
template<int NKQ, int RS, int UNROLL>
__device__ __forceinline__ void gates_accum4(
    const float* __restrict__ w, const ull* __restrict__ v, int lane,
    ull aR[2][4], ull aZ[2][4], ull aN[2][4])
{
    #pragma unroll UNROLL
    for(int kq = 0; kq < NKQ; kq++){
        float4 wra = *(const float4*)(w + (      lane)*RS + kq*4);
        float4 wrb = *(const float4*)(w + ( 32 + lane)*RS + kq*4);
        float4 wza = *(const float4*)(w + ( 64 + lane)*RS + kq*4);
        float4 wzb = *(const float4*)(w + ( 96 + lane)*RS + kq*4);
        float4 wna = *(const float4*)(w + (128 + lane)*RS + kq*4);
        float4 wnb = *(const float4*)(w + (160 + lane)*RS + kq*4);
        #pragma unroll
        for(int i = 0; i < 4; i++){
            int k = kq*4 + i;
            ulonglong2 v01 = *(const ulonglong2*)(v + k*4);
            ulonglong2 v23 = *(const ulonglong2*)(v + k*4 + 2);
            float fra=(&wra.x)[i], frb=(&wrb.x)[i];
            float fza=(&wza.x)[i], fzb=(&wzb.x)[i];
            float fna=(&wna.x)[i], fnb=(&wnb.x)[i];
            ull ra=pack2(fra,fra), rb=pack2(frb,frb);
            ull za=pack2(fza,fza), zb=pack2(fzb,fzb);
            ull na=pack2(fna,fna), nb=pack2(fnb,fnb);
            aR[0][0]=fma2(v01.x,ra,aR[0][0]); aR[0][1]=fma2(v01.y,ra,aR[0][1]);
            aR[0][2]=fma2(v23.x,ra,aR[0][2]); aR[0][3]=fma2(v23.y,ra,aR[0][3]);
            aR[1][0]=fma2(v01.x,rb,aR[1][0]); aR[1][1]=fma2(v01.y,rb,aR[1][1]);
            aR[1][2]=fma2(v23.x,rb,aR[1][2]); aR[1][3]=fma2(v23.y,rb,aR[1][3]);
            aZ[0][0]=fma2(v01.x,za,aZ[0][0]); aZ[0][1]=fma2(v01.y,za,aZ[0][1]);
            aZ[0][2]=fma2(v23.x,za,aZ[0][2]); aZ[0][3]=fma2(v23.y,za,aZ[0][3]);
            aZ[1][0]=fma2(v01.x,zb,aZ[1][0]); aZ[1][1]=fma2(v01.y,zb,aZ[1][1]);
            aZ[1][2]=fma2(v23.x,zb,aZ[1][2]); aZ[1][3]=fma2(v23.y,zb,aZ[1][3]);
            aN[0][0]=fma2(v01.x,na,aN[0][0]); aN[0][1]=fma2(v01.y,na,aN[0][1]);
            aN[0][2]=fma2(v23.x,na,aN[0][2]); aN[0][3]=fma2(v23.y,na,aN[0][3]);
            aN[1][0]=fma2(v01.x,nb,aN[1][0]); aN[1][1]=fma2(v01.y,nb,aN[1][1]);
            aN[1][2]=fma2(v23.x,nb,aN[1][2]); aN[1][3]=fma2(v23.y,nb,aN[1][3]);
        }
    }
}

// One GRU step for this warp's 8 elements.
__device__ __forceinline__ void gru_step(
    const float* __restrict__ wiT, const float* __restrict__ wT,
    ull* __restrict__ hv2, const ull* __restrict__ xv2, int lane,
    const ull br2[2], const ull bz2[2], const ull bni2[2], const ull bnh2[2])
{
    ull aR[2][4], aZ[2][4], aNi[2][4], aHn[2][4];
    #pragma unroll
    for(int rr = 0; rr < 2; rr++){
        #pragma unroll
        for(int p = 0; p < 4; p++){
            aR[rr][p]=br2[rr]; aZ[rr][p]=bz2[rr];
            aNi[rr][p]=bni2[rr]; aHn[rr][p]=bnh2[rr];
        }
    }
    gates_accum4<IN_DIM/4, WISTRIDE, 4>(wiT, xv2, lane, aR, aZ, aNi);
    gates_accum4<HH/4,     WSTRIDE,  2>(wT,  hv2, lane, aR, aZ, aHn);

    // read old h for own rows
    ulonglong2 old01[2], old23[2];
    #pragma unroll
    for(int rr = 0; rr < 2; rr++){
        int j = lane + rr*32;
        old01[rr] = *(const ulonglong2*)(hv2 + j*4);
        old23[rr] = *(const ulonglong2*)(hv2 + j*4 + 2);
    }
    __syncwarp();    // gate reads of h complete

    #pragma unroll
    for(int rr = 0; rr < 2; rr++){
        int j = lane + rr*32;
        float hold[8];
        { float2 t;
          t=unpack2(old01[rr].x); hold[0]=t.x; hold[1]=t.y;
          t=unpack2(old01[rr].y); hold[2]=t.x; hold[3]=t.y;
          t=unpack2(old23[rr].x); hold[4]=t.x; hold[5]=t.y;
          t=unpack2(old23[rr].y); hold[6]=t.x; hold[7]=t.y; }
        float hn[8];
        #pragma unroll
        for(int p = 0; p < 4; p++){
            float2 r2  = unpack2(aR[rr][p]),  z2  = unpack2(aZ[rr][p]);
            float2 ni2 = unpack2(aNi[rr][p]), nh2 = unpack2(aHn[rr][p]);
            float r0 = sigm(r2.x), r1 = sigm(r2.y);
            float z0 = sigm(z2.x), z1 = sigm(z2.y);
            float n0 = tanhapx(fmaf(r0, nh2.x, ni2.x));
            float n1 = tanhapx(fmaf(r1, nh2.y, ni2.y));
            hn[2*p]   = fmaf(z0, hold[2*p]   - n0, n0);
            hn[2*p+1] = fmaf(z1, hold[2*p+1] - n1, n1);
        }
        ulonglong2 s01, s23;
        s01.x = pack2(hn[0],hn[1]); s01.y = pack2(hn[2],hn[3]);
        s23.x = pack2(hn[4],hn[5]); s23.y = pack2(hn[6],hn[7]);
        *(ulonglong2*)(hv2 + j*4)     = s01;
        *(ulonglong2*)(hv2 + j*4 + 2) = s23;
    }
    __syncwarp();    // h writes visible
}

// tiny kernel for ncu launch-parity only
__global__ void nop_kernel(){}

// ---------------------------------------------------------------------------
// Kernel 1: encoder (128 steps) + decoder (100 steps), warp-autonomous
// ---------------------------------------------------------------------------
__global__ void __launch_bounds__(THREADS1, 1) seq_kernel(
    const float* __restrict__ x,    const float* __restrict__ trg,
    const float* __restrict__ eWih, const float* __restrict__ ebih,
    const float* __restrict__ eWhh, const float* __restrict__ ebhh,
    const float* __restrict__ dWih, const float* __restrict__ dbih,
    const float* __restrict__ dWhh, const float* __restrict__ dbhh,
    const float* __restrict__ outW, const float* __restrict__ outb,
    const float* __restrict__ embW, const float* __restrict__ embb)
{
    extern __shared__ unsigned char smem_raw[];
    Smem& s = *reinterpret_cast<Smem*>(smem_raw);
    const int tid  = threadIdx.x;
    const int w    = tid >> 5;
    const int lane = tid & 31;
    const int warpB = (blockIdx.x*4 + w)*8;   // base batch index

    // ---- stage encoder weights (row-native, padded stride) ----
    for(int i = tid; i < 192*HH; i += THREADS1){
        int r = i >> 6, k = i & 63;
        s.wT[r*WSTRIDE + k] = eWhh[i];
    }
    for(int i = tid; i < 192*IN_DIM; i += THREADS1){
        int r = i >> 4, d = i & 15;
        s.wiT[r*WISTRIDE + d] = eWih[i];
    }
    for(int i = tid; i < 16*HH; i += THREADS1){
        int dd = i >> 6, k = i & 63;
        s.outw[dd*OWSTRIDE + k] = outW[i];
    }
    __syncthreads();

    ull* hv2 = s.h2[w];

    // zero own h rows
    #pragma unroll
    for(int rr = 0; rr < 2; rr++){
        int j = lane + rr*32;
        ulonglong2 z; z.x = 0ull; z.y = 0ull;
        *(ulonglong2*)(hv2 + j*4)     = z;
        *(ulonglong2*)(hv2 + j*4 + 2) = z;
    }

    // packed encoder biases
    ull br2[2], bz2[2], bni2[2], bnh2[2];
    #pragma unroll
    for(int rr = 0; rr < 2; rr++){
        int j = lane + rr*32;
        float br = ebih[j] + ebhh[j];
        float bz = ebih[64+j] + ebhh[64+j];
        br2[rr]  = pack2(br, br);
        bz2[rr]  = pack2(bz, bz);
        bni2[rr] = pack2(ebih[128+j], ebih[128+j]);
        bnh2[rr] = pack2(ebhh[128+j], ebhh[128+j]);
    }

    // x gather mapping: lane -> (elem e, dims d0..d0+3)
    const int e  = lane >> 2;
    const int d0 = (lane & 3) * 4;
    const float* xbase = x + ((size_t)(warpB + e)*SRC_LEN)*IN_DIM + d0;

    // preload x[0] into buf 0
    {
        float4 xv = *(const float4*)xbase;
        float* xf0 = (float*)s.x2[w][0];
        xf0[(d0+0)*8 + e] = xv.x;
        xf0[(d0+1)*8 + e] = xv.y;
        xf0[(d0+2)*8 + e] = xv.z;
        xf0[(d0+3)*8 + e] = xv.w;
    }
    __syncwarp();

    // ================= encoder =================
    for(int t = 0; t < SRC_LEN; t++){
        int cur = t & 1, nxt = cur ^ 1;
        float4 xv;
        if(t + 1 < SRC_LEN)
            xv = *(const float4*)(xbase + (size_t)(t+1)*IN_DIM);

        // store next-step x into the other buffer (no sync needed: disjoint)
        if(t + 1 < SRC_LEN){
            float* xfn = (float*)s.x2[w][nxt];
            xfn[(d0+0)*8 + e] = xv.x;
            xfn[(d0+1)*8 + e] = xv.y;
            xfn[(d0+2)*8 + e] = xv.z;
            xfn[(d0+3)*8 + e] = xv.w;
        }
        gru_step(s.wiT, s.wT, hv2, s.x2[w][cur], lane, br2, bz2, bni2, bnh2);
    }

    // ---- switch to decoder weights ----
    __syncthreads();
    for(int i = tid; i < 192*HH; i += THREADS1){
        int r = i >> 6, k = i & 63;
        s.wT[r*WSTRIDE + k] = dWhh[i];
    }
    for(int i = tid; i < 192*IN_DIM; i += THREADS1){
        int r = i >> 4, d = i & 15;
        s.wiT[r*WISTRIDE + d] = dWih[i];
    }
    __syncthreads();

    // decoder biases
    #pragma unroll
    for(int rr = 0; rr < 2; rr++){
        int j = lane + rr*32;
        float br = dbih[j] + dbhh[j];
        float bz = dbih[64+j] + dbhh[64+j];
        br2[rr]  = pack2(br, br);
        bz2[rr]  = pack2(bz, bz);
        bni2[rr] = pack2(dbih[128+j], dbih[128+j]);
        bnh2[rr] = pack2(dbhh[128+j], dbhh[128+j]);
    }

    // initial decoder input: emb(trg) -> buf 0
    {
        float4 tv = *(const float4*)(trg + (size_t)(warpB + e)*4);
        float* xf0 = (float*)s.x2[w][0];
        #pragma unroll
        for(int i = 0; i < 4; i++){
            int d = d0 + i;
            float a = embb[d] + embW[d*4+0]*tv.x + embW[d*4+1]*tv.y
                              + embW[d*4+2]*tv.z + embW[d*4+3]*tv.w;
            xf0[d*8 + e] = a;
        }
    }
    const int dd  = lane >> 1;          // out dim 0..15
    const int pp0 = (lane & 1)*2;       // elem-pair base (0 or 2)
    const float ob = outb[dd];
    __syncwarp();

    // ================= decoder =================
    for(int t = 0; t < SEQ_LEN; t++){
        int cur = t & 1, nxt = cur ^ 1;
        gru_step(s.wiT, s.wT, hv2, s.x2[w][cur], lane, br2, bz2, bni2, bnh2);

        // out projection: lane computes o[dd] for 4 elems (pairs pp0, pp0+1)
        ull o20 = pack2(ob, ob), o21 = pack2(ob, ob);
        #pragma unroll 4
        for(int kq = 0; kq < 16; kq++){
            float4 wv4 = *(const float4*)(s.outw + dd*OWSTRIDE + kq*4);
            #pragma unroll
            for(int i = 0; i < 4; i++){
                int k = kq*4 + i;
                ulonglong2 hp = *(const ulonglong2*)(hv2 + k*4 + pp0);
                float wv = (&wv4.x)[i];
                ull wp = pack2(wv, wv);
                o20 = fma2(hp.x, wp, o20);
                o21 = fma2(hp.y, wp, o21);
            }
        }
        float2 oa = unpack2(o20), obp = unpack2(o21);
        int e0 = pp0*2;                 // 0 or 4
        float* xfn = (float*)s.x2[w][nxt];
        xfn[dd*8 + e0]     = oa.x;
        xfn[dd*8 + e0 + 1] = oa.y;
        xfn[dd*8 + e0 + 2] = obp.x;
        xfn[dd*8 + e0 + 3] = obp.y;
        size_t gb = ((size_t)(warpB + e0)*SEQ_LEN + t)*IN_DIM + dd;
        const size_t ES = (size_t)SEQ_LEN*IN_DIM;
        g_dec[gb]        = oa.x;
        g_dec[gb + ES]   = oa.y;
        g_dec[gb + 2*ES] = obp.x;
        g_dec[gb + 3*ES] = obp.y;
        __syncwarp();
    }
}

// ---------------------------------------------------------------------------
// A&S 7.1.26 erf-based exact GELU (|erf err| <= 1.5e-7)
// ---------------------------------------------------------------------------
__device__ __forceinline__ float gelu_exact(float x){
    const float A1 =  0.254829592f, A2 = -0.284496736f, A3 = 1.421413741f;
    const float A4 = -1.453152027f, A5 =  1.061405429f, P  = 0.3275911f;
    float sarg = 0.70710678118654752f * x;
    float a = fabsf(sarg);
    float t = __fdividef(1.f, fmaf(P, a, 1.f));
    float poly = t*fmaf(t, fmaf(t, fmaf(t, fmaf(t, A5, A4), A3), A2), A1);
    float erf = fmaf(-poly, __expf(-a*a), 1.f);
    erf = copysignf(erf, sarg);
    return 0.5f * x * (1.f + erf);
}

// ---------------------------------------------------------------------------
// Kernel 2: output heads, 2 rows per thread, f32x2
// ---------------------------------------------------------------------------
__global__ void __launch_bounds__(256) heads_kernel(
    const float* __restrict__ mhW1, const float* __restrict__ mhb1,
    const float* __restrict__ mhW2, const float* __restrict__ mhb2,
    const float* __restrict__ chW1, const float* __restrict__ chb1,
    const float* __restrict__ chW2, const float* __restrict__ chb2,
    float* __restrict__ out)
{
    __shared__ __align__(16) float w1m[HH*IN_DIM], w1c[HH*IN_DIM];
    __shared__ __align__(16) ull  w2mP[HH*2];
    __shared__ __align__(16) ull  w2cP[HH*5];
    __shared__ float b1m[HH], b1c[HH];
    __shared__ float b2m[MEAN_DIM], b2c[COV_DIM];

    int tid = threadIdx.x;
    for(int i = tid; i < HH*IN_DIM; i += 256){ w1m[i] = mhW1[i]; w1c[i] = chW1[i]; }
    for(int i = tid; i < HH*2; i += 256){
        int u = i >> 1, mp = i & 1;
        w2mP[i] = pack2(mhW2[(2*mp)*HH + u], mhW2[(2*mp+1)*HH + u]);
    }
    for(int i = tid; i < HH*5; i += 256){
        int u = i / 5, vp = i - u*5;
        w2cP[i] = pack2(chW2[(2*vp)*HH + u], chW2[(2*vp+1)*HH + u]);
    }
    if(tid < HH){ b1m[tid] = mhb1[tid]; b1c[tid] = chb1[tid]; }
    if(tid < MEAN_DIM) b2m[tid] = mhb2[tid];
    if(tid < COV_DIM)  b2c[tid] = chb2[tid];
    __syncthreads();

    int r0 = (blockIdx.x*256 + tid)*2;      // rows r0, r0+1
    const ulonglong2* opA = (const ulonglong2*)&g_dec[(size_t)r0*IN_DIM];
    ulonglong2 qa0 = opA[0], qa1 = opA[1], qa2 = opA[2], qa3 = opA[3];
    ulonglong2 qb0 = opA[4], qb1 = opA[5], qb2 = opA[6], qb3 = opA[7];
    ull ovA[8] = { qa0.x,qa0.y,qa1.x,qa1.y,qa2.x,qa2.y,qa3.x,qa3.y };
    ull ovB[8] = { qb0.x,qb0.y,qb1.x,qb1.y,qb2.x,qb2.y,qb3.x,qb3.y };

    ull amA[2], amB[2], acA[5], acB[5];
    amA[0] = amB[0] = pack2(b2m[0], b2m[1]);
    amA[1] = amB[1] = pack2(b2m[2], b2m[3]);
    #pragma unroll
    for(int vp = 0; vp < 5; vp++) acA[vp] = acB[vp] = pack2(b2c[2*vp], b2c[2*vp+1]);

    #pragma unroll 4
    for(int u = 0; u < HH; u++){
        const ull* w1mp = (const ull*)(w1m + u*16);
        const ull* w1cp = (const ull*)(w1c + u*16);
        ull a1A = 0, a1B = 0, a2A = 0, a2B = 0;
        #pragma unroll
        for(int i = 0; i < 8; i++){
            ull wm = w1mp[i], wc = w1cp[i];
            a1A = fma2(ovA[i], wm, a1A);
            a1B = fma2(ovB[i], wm, a1B);
            a2A = fma2(ovA[i], wc, a2A);
            a2B = fma2(ovB[i], wc, a2B);
        }
        float2 f;
        f = unpack2(a1A); float s1A = b1m[u] + f.x + f.y;
        f = unpack2(a1B); float s1B = b1m[u] + f.x + f.y;
        f = unpack2(a2A); float s2A = b1c[u] + f.x + f.y;
        f = unpack2(a2B); float s2B = b1c[u] + f.x + f.y;
        float g1A = gelu_exact(s1A), g1B = gelu_exact(s1B);
        float g2A = gelu_exact(s2A), g2B = gelu_exact(s2B);
        ull g1Ap = pack2(g1A, g1A), g1Bp = pack2(g1B, g1B);
        ull g2Ap = pack2(g2A, g2A), g2Bp = pack2(g2B, g2B);
        ull wm0 = w2mP[u*2], wm1 = w2mP[u*2+1];
        amA[0] = fma2(g1Ap, wm0, amA[0]); amA[1] = fma2(g1Ap, wm1, amA[1]);
        amB[0] = fma2(g1Bp, wm0, amB[0]); amB[1] = fma2(g1Bp, wm1, amB[1]);
        #pragma unroll
        for(int vp = 0; vp < 5; vp++){
            ull wcv = w2cP[u*5+vp];
            acA[vp] = fma2(g2Ap, wcv, acA[vp]);
            acB[vp] = fma2(g2Bp, wcv, acB[vp]);
        }
    }

    // clamp means dims 2,3 to [-1,1]
    { float2 m = unpack2(amA[1]);
      m.x = fminf(fmaxf(m.x, -1.f), 1.f); m.y = fminf(fmaxf(m.y, -1.f), 1.f);
      amA[1] = pack2(m.x, m.y); }
    { float2 m = unpack2(amB[1]);
      m.x = fminf(fmaxf(m.x, -1.f), 1.f); m.y = fminf(fmaxf(m.y, -1.f), 1.f);
      amB[1] = pack2(m.x, m.y); }

    ull* om = (ull*)(out + MEANS_OFF) + (size_t)r0*2;
    om[0] = amA[0]; om[1] = amA[1]; om[2] = amB[0]; om[3] = amB[1];
    ull* oc = (ull*)(out + COVS_OFF) + (size_t)r0*5;
    #pragma unroll
    for(int vp = 0; vp < 5; vp++){ oc[vp] = acA[vp]; oc[5+vp] = acB[vp]; }
}

// ---------------------------------------------------------------------------
extern "C" void kernel_launch(void* const* d_in, const int* in_sizes, int n_in,
                              void* d_out, int out_size)
{
    const float* x     = (const float*)d_in[0];
    const float* trg   = (const float*)d_in[1];
    const float* eWih  = (const float*)d_in[2];
    const float* ebih  = (const float*)d_in[3];
    const float* eWhh  = (const float*)d_in[4];
    const float* ebhh  = (const float*)d_in[5];
    const float* dWih  = (const float*)d_in[6];
    const float* dbih  = (const float*)d_in[7];
    const float* dWhh  = (const float*)d_in[8];
    const float* dbhh  = (const float*)d_in[9];
    const float* outW  = (const float*)d_in[10];
    const float* outb  = (const float*)d_in[11];
    const float* embW  = (const float*)d_in[12];
    const float* embb  = (const float*)d_in[13];
    const float* mhW1  = (const float*)d_in[14];
    const float* mhb1  = (const float*)d_in[15];
    const float* mhW2  = (const float*)d_in[16];
    const float* mhb2  = (const float*)d_in[17];
    const float* chW1  = (const float*)d_in[18];
    const float* chb1  = (const float*)d_in[19];
    const float* chW2  = (const float*)d_in[20];
    const float* chb2  = (const float*)d_in[21];

    cudaFuncSetAttribute(seq_kernel, cudaFuncAttributeMaxDynamicSharedMemorySize,
                         (int)sizeof(Smem));

    // launch-parity pattern [nop, seq, nop, heads]: with ncu -s 5 -c 1 the
    // 6th launch in the process is seq_kernel -> finally get seq profile.
    nop_kernel<<<1, 32>>>();
    seq_kernel<<<GRID1, THREADS1, sizeof(Smem)>>>(
        x, trg, eWih, ebih, eWhh, ebhh, dWih, dbih, dWhh, dbhh,
        outW, outb, embW, embb);
    nop_kernel<<<1, 32>>>();
    heads_kernel<<<(BB*SEQ_LEN)/512, 256>>>(
        mhW1, mhb1, mhW2, mhb2, chW1, chb1, chW2, chb2, (float*)d_out);
}

// round 9
// speedup vs baseline: 1.3936x; 1.0462x over previous
#include <cuda_runtime.h>
#include <math.h>

#define BB       4096
#define SRC_LEN  128
#define IN_DIM   16
#define HH       64
#define SEQ_LEN  100
#define MEAN_DIM 4
#define COV_DIM  10

#define THREADS1 256             // 8 warps per CTA, 2 per SMSP
#define NWARP    8
#define EPW      4               // elements per warp
#define GRID1    128             // 128 * 8 * 4 = 4096
#define MEANS_OFF 0
#define COVS_OFF  (BB*SEQ_LEN*MEAN_DIM)

#define WSTRIDE   68             // padded row stride (floats) for Whh rows
#define WISTRIDE  20             // padded row stride for Wih rows
#define OWSTRIDE  68             // padded row stride for outW rows

typedef unsigned long long ull;

// decoder output scratch [B][SEQ_LEN][IN_DIM]
__device__ __align__(16) float g_dec[BB*SEQ_LEN*IN_DIM];

// ---------------------------------------------------------------------------
// f32x2 packed helpers
// ---------------------------------------------------------------------------
__device__ __forceinline__ ull pack2(float x, float y){
    ull r; asm("mov.b64 %0,{%1,%2};" : "=l"(r) : "f"(x), "f"(y)); return r;
}
__device__ __forceinline__ float2 unpack2(ull v){
    float2 r; asm("mov.b64 {%0,%1},%2;" : "=f"(r.x), "=f"(r.y) : "l"(v)); return r;
}
__device__ __forceinline__ ull fma2(ull a, ull b, ull c){
    ull d; asm("fma.rn.f32x2 %0,%1,%2,%3;" : "=l"(d) : "l"(a), "l"(b), "l"(c)); return d;
}
__device__ __forceinline__ float tanhapx(float x){
    float y; asm("tanh.approx.f32 %0,%1;" : "=f"(y) : "f"(x)); return y;
}
// sigmoid(x) = 0.5 + 0.5*tanh(0.5x)  (1 MUFU)
__device__ __forceinline__ float sigm(float x){
    return fmaf(tanhapx(0.5f*x), 0.5f, 0.5f);
}

// ---------------------------------------------------------------------------
// SMEM (~84 KB dynamic)
// per-warp h layout: hv2[j*2 + p] (j = h-row, p = elem-pair 0/1)
// per-warp x layout: xv2[d*2 + p]
// ---------------------------------------------------------------------------
struct Smem {
    __align__(16) float wT [192*WSTRIDE];     // Whh rows, padded stride
    __align__(16) float wiT[192*WISTRIDE];    // Wih rows, padded stride
    __align__(16) float outw[16*OWSTRIDE];    // outW rows, padded stride
    __align__(16) ull   h2[NWARP][HH*2];
    __align__(16) ull   x2[NWARP][2][IN_DIM*2];
};

// ---------------------------------------------------------------------------
// Gate accumulation: rows (lane, lane+32), 2 elem-pairs. 12 fma2 per k.
// ---------------------------------------------------------------------------
template<int NKQ, int RS, int UNROLL>
__device__ __forceinline__ void gates_accum4(
    const float* __restrict__ w, const ull* __restrict__ v, int lane,
    ull aR[2][2], ull aZ[2][2], ull aN[2][2])
{
    #pragma unroll UNROLL
    for(int kq = 0; kq < NKQ; kq++){
        float4 wra = *(const float4*)(w + (      lane)*RS + kq*4);
        float4 wrb = *(const float4*)(w + ( 32 + lane)*RS + kq*4);
        float4 wza = *(const float4*)(w + ( 64 + lane)*RS + kq*4);
        float4 wzb = *(const float4*)(w + ( 96 + lane)*RS + kq*4);
        float4 wna = *(const float4*)(w + (128 + lane)*RS + kq*4);
        float4 wnb = *(const float4*)(w + (160 + lane)*RS + kq*4);
        #pragma unroll
        for(int i = 0; i < 4; i++){
            int k = kq*4 + i;
            ulonglong2 v01 = *(const ulonglong2*)(v + k*2);
            float fra=(&wra.x)[i], frb=(&wrb.x)[i];
            float fza=(&wza.x)[i], fzb=(&wzb.x)[i];
            float fna=(&wna.x)[i], fnb=(&wnb.x)[i];
            ull ra=pack2(fra,fra), rb=pack2(frb,frb);
            ull za=pack2(fza,fza), zb=pack2(fzb,fzb);
            ull na=pack2(fna,fna), nb=pack2(fnb,fnb);
            aR[0][0]=fma2(v01.x,ra,aR[0][0]); aR[0][1]=fma2(v01.y,ra,aR[0][1]);
            aR[1][0]=fma2(v01.x,rb,aR[1][0]); aR[1][1]=fma2(v01.y,rb,aR[1][1]);
            aZ[0][0]=fma2(v01.x,za,aZ[0][0]); aZ[0][1]=fma2(v01.y,za,aZ[0][1]);
            aZ[1][0]=fma2(v01.x,zb,aZ[1][0]); aZ[1][1]=fma2(v01.y,zb,aZ[1][1]);
            aN[0][0]=fma2(v01.x,na,aN[0][0]); aN[0][1]=fma2(v01.y,na,aN[0][1]);
            aN[1][0]=fma2(v01.x,nb,aN[1][0]); aN[1][1]=fma2(v01.y,nb,aN[1][1]);
        }
    }
}

// One GRU step for this warp's 4 elements.
__device__ __forceinline__ void gru_step(
    const float* __restrict__ wiT, const float* __restrict__ wT,
    ull* __restrict__ hv2, const ull* __restrict__ xv2, int lane,
    const ull br2[2], const ull bz2[2], const ull bni2[2], const ull bnh2[2])
{
    ull aR[2][2], aZ[2][2], aNi[2][2], aHn[2][2];
    #pragma unroll
    for(int rr = 0; rr < 2; rr++){
        #pragma unroll
        for(int p = 0; p < 2; p++){
            aR[rr][p]=br2[rr]; aZ[rr][p]=bz2[rr];
            aNi[rr][p]=bni2[rr]; aHn[rr][p]=bnh2[rr];
        }
    }
    gates_accum4<IN_DIM/4, WISTRIDE, 4>(wiT, xv2, lane, aR, aZ, aNi);
    gates_accum4<HH/4,     WSTRIDE,  4>(wT,  hv2, lane, aR, aZ, aHn);

    // read old h for own rows
    ulonglong2 old[2];
    #pragma unroll
    for(int rr = 0; rr < 2; rr++){
        int j = lane + rr*32;
        old[rr] = *(const ulonglong2*)(hv2 + j*2);
    }
    __syncwarp();    // gate reads of h complete

    #pragma unroll
    for(int rr = 0; rr < 2; rr++){
        int j = lane + rr*32;
        float hold[4];
        { float2 t;
          t=unpack2(old[rr].x); hold[0]=t.x; hold[1]=t.y;
          t=unpack2(old[rr].y); hold[2]=t.x; hold[3]=t.y; }
        float hn[4];
        #pragma unroll
        for(int p = 0; p < 2; p++){
            float2 r2  = unpack2(aR[rr][p]),  z2  = unpack2(aZ[rr][p]);
            float2 ni2 = unpack2(aNi[rr][p]), nh2 = unpack2(aHn[rr][p]);
            float r0 = sigm(r2.x), r1 = sigm(r2.y);
            float z0 = sigm(z2.x), z1 = sigm(z2.y);
            float n0 = tanhapx(fmaf(r0, nh2.x, ni2.x));
            float n1 = tanhapx(fmaf(r1, nh2.y, ni2.y));
            hn[2*p]   = fmaf(z0, hold[2*p]   - n0, n0);
            hn[2*p+1] = fmaf(z1, hold[2*p+1] - n1, n1);
        }
        ulonglong2 sN;
        sN.x = pack2(hn[0],hn[1]); sN.y = pack2(hn[2],hn[3]);
        *(ulonglong2*)(hv2 + j*2) = sN;
    }
    __syncwarp();    // h writes visible
}

// ---------------------------------------------------------------------------
// Kernel 1: encoder (128 steps) + decoder (100 steps), warp-autonomous
// ---------------------------------------------------------------------------
__global__ void __launch_bounds__(THREADS1, 1) seq_kernel(
    const float* __restrict__ x,    const float* __restrict__ trg,
    const float* __restrict__ eWih, const float* __restrict__ ebih,
    const float* __restrict__ eWhh, const float* __restrict__ ebhh,
    const float* __restrict__ dWih, const float* __restrict__ dbih,
    const float* __restrict__ dWhh, const float* __restrict__ dbhh,
    const float* __restrict__ outW, const float* __restrict__ outb,
    const float* __restrict__ embW, const float* __restrict__ embb)
{
    extern __shared__ unsigned char smem_raw[];
    Smem& s = *reinterpret_cast<Smem*>(smem_raw);
    const int tid  = threadIdx.x;
    const int w    = tid >> 5;
    const int lane = tid & 31;
    const int warpB = (blockIdx.x*NWARP + w)*EPW;   // base batch index

    // ---- stage encoder weights (row-native, padded stride) ----
    for(int i = tid; i < 192*HH; i += THREADS1){
        int r = i >> 6, k = i & 63;
        s.wT[r*WSTRIDE + k] = eWhh[i];
    }
    for(int i = tid; i < 192*IN_DIM; i += THREADS1){
        int r = i >> 4, d = i & 15;
        s.wiT[r*WISTRIDE + d] = eWih[i];
    }
    for(int i = tid; i < 16*HH; i += THREADS1){
        int dd = i >> 6, k = i & 63;
        s.outw[dd*OWSTRIDE + k] = outW[i];
    }
    __syncthreads();

    ull* hv2 = s.h2[w];

    // zero own h rows
    #pragma unroll
    for(int rr = 0; rr < 2; rr++){
        int j = lane + rr*32;
        ulonglong2 z; z.x = 0ull; z.y = 0ull;
        *(ulonglong2*)(hv2 + j*2) = z;
    }

    // packed encoder biases
    ull br2[2], bz2[2], bni2[2], bnh2[2];
    #pragma unroll
    for(int rr = 0; rr < 2; rr++){
        int j = lane + rr*32;
        float br = ebih[j] + ebhh[j];
        float bz = ebih[64+j] + ebhh[64+j];
        br2[rr]  = pack2(br, br);
        bz2[rr]  = pack2(bz, bz);
        bni2[rr] = pack2(ebih[128+j], ebih[128+j]);
        bnh2[rr] = pack2(ebhh[128+j], ebhh[128+j]);
    }

    // x gather mapping: lane -> (elem e = lane>>3, dims d0, d0+1)
    const int e  = lane >> 3;           // 0..3
    const int d0 = (lane & 7) * 2;      // 0,2,..,14
    const float* xbase = x + ((size_t)(warpB + e)*SRC_LEN)*IN_DIM + d0;

    // preload x[0] into buf 0
    {
        float2 xv = *(const float2*)xbase;
        float* xf0 = (float*)s.x2[w][0];
        xf0[(d0+0)*4 + e] = xv.x;
        xf0[(d0+1)*4 + e] = xv.y;
    }
    __syncwarp();

    // ================= encoder =================
    for(int t = 0; t < SRC_LEN; t++){
        int cur = t & 1, nxt = cur ^ 1;
        if(t + 1 < SRC_LEN){
            float2 xv = *(const float2*)(xbase + (size_t)(t+1)*IN_DIM);
            float* xfn = (float*)s.x2[w][nxt];
            xfn[(d0+0)*4 + e] = xv.x;
            xfn[(d0+1)*4 + e] = xv.y;
        }
        gru_step(s.wiT, s.wT, hv2, s.x2[w][cur], lane, br2, bz2, bni2, bnh2);
    }

    // ---- switch to decoder weights ----
    __syncthreads();
    for(int i = tid; i < 192*HH; i += THREADS1){
        int r = i >> 6, k = i & 63;
        s.wT[r*WSTRIDE + k] = dWhh[i];
    }
    for(int i = tid; i < 192*IN_DIM; i += THREADS1){
        int r = i >> 4, d = i & 15;
        s.wiT[r*WISTRIDE + d] = dWih[i];
    }
    __syncthreads();

    // decoder biases
    #pragma unroll
    for(int rr = 0; rr < 2; rr++){
        int j = lane + rr*32;
        float br = dbih[j] + dbhh[j];
        float bz = dbih[64+j] + dbhh[64+j];
        br2[rr]  = pack2(br, br);
        bz2[rr]  = pack2(bz, bz);
        bni2[rr] = pack2(dbih[128+j], dbih[128+j]);
        bnh2[rr] = pack2(dbhh[128+j], dbhh[128+j]);
    }

    // initial decoder input: emb(trg) -> buf 0
    if(lane < 16){
        int ee = lane >> 2;             // 0..3
        int dbase = (lane & 3) * 4;     // 0,4,8,12
        float4 tv = *(const float4*)(trg + (size_t)(warpB + ee)*4);
        float* xf0 = (float*)s.x2[w][0];
        #pragma unroll
        for(int i = 0; i < 4; i++){
            int d = dbase + i;
            float a = embb[d] + embW[d*4+0]*tv.x + embW[d*4+1]*tv.y
                              + embW[d*4+2]*tv.z + embW[d*4+3]*tv.w;
            xf0[d*4 + ee] = a;
        }
    }
    const int dd = lane >> 1;          // out dim 0..15
    const int pp = lane & 1;           // elem-pair (0 or 1)
    const float ob = outb[dd];
    __syncwarp();

    // ================= decoder =================
    for(int t = 0; t < SEQ_LEN; t++){
        int cur = t & 1, nxt = cur ^ 1;
        gru_step(s.wiT, s.wT, hv2, s.x2[w][cur], lane, br2, bz2, bni2, bnh2);

        // out projection: lane computes o[dd] for its elem-pair (2 elems)
        ull o2 = pack2(ob, ob);
        #pragma unroll 4
        for(int kq = 0; kq < 16; kq++){
            float4 wv4 = *(const float4*)(s.outw + dd*OWSTRIDE + kq*4);
            #pragma unroll
            for(int i = 0; i < 4; i++){
                int k = kq*4 + i;
                ull hp = hv2[k*2 + pp];
                float wv = (&wv4.x)[i];
                o2 = fma2(hp, pack2(wv, wv), o2);
            }
        }
        float2 oa = unpack2(o2);
        int e0 = pp*2;
        float* xfn = (float*)s.x2[w][nxt];
        xfn[dd*4 + e0]     = oa.x;
        xfn[dd*4 + e0 + 1] = oa.y;
        size_t gb = ((size_t)(warpB + e0)*SEQ_LEN + t)*IN_DIM + dd;
        const size_t ES = (size_t)SEQ_LEN*IN_DIM;
        g_dec[gb]      = oa.x;
        g_dec[gb + ES] = oa.y;
        __syncwarp();
    }
}

// ---------------------------------------------------------------------------
// A&S 7.1.26 erf-based exact GELU (|erf err| <= 1.5e-7)
// ---------------------------------------------------------------------------
__device__ __forceinline__ float gelu_exact(float x){
    const float A1 =  0.254829592f, A2 = -0.284496736f, A3 = 1.421413741f;
    const float A4 = -1.453152027f, A5 =  1.061405429f, P  = 0.3275911f;
    float sarg = 0.70710678118654752f * x;
    float a = fabsf(sarg);
    float t = __fdividef(1.f, fmaf(P, a, 1.f));
    float poly = t*fmaf(t, fmaf(t, fmaf(t, fmaf(t, A5, A4), A3), A2), A1);
    float erf = fmaf(-poly, __expf(-a*a), 1.f);
    erf = copysignf(erf, sarg);
    return 0.5f * x * (1.f + erf);
}

// ---------------------------------------------------------------------------
// Kernel 2: output heads, 2 rows per thread, f32x2
// ---------------------------------------------------------------------------
__global__ void __launch_bounds__(256) heads_kernel(
    const float* __restrict__ mhW1, const float* __restrict__ mhb1,
    const float* __restrict__ mhW2, const float* __restrict__ mhb2,
    const float* __restrict__ chW1, const float* __restrict__ chb1,
    const float* __restrict__ chW2, const float* __restrict__ chb2,
    float* __restrict__ out)
{
    __shared__ __align__(16) float w1m[HH*IN_DIM], w1c[HH*IN_DIM];
    __shared__ __align__(16) ull  w2mP[HH*2];
    __shared__ __align__(16) ull  w2cP[HH*5];
    __shared__ float b1m[HH], b1c[HH];
    __shared__ float b2m[MEAN_DIM], b2c[COV_DIM];

    int tid = threadIdx.x;
    for(int i = tid; i < HH*IN_DIM; i += 256){ w1m[i] = mhW1[i]; w1c[i] = chW1[i]; }
    for(int i = tid; i < HH*2; i += 256){
        int u = i >> 1, mp = i & 1;
        w2mP[i] = pack2(mhW2[(2*mp)*HH + u], mhW2[(2*mp+1)*HH + u]);
    }
    for(int i = tid; i < HH*5; i += 256){
        int u = i / 5, vp = i - u*5;
        w2cP[i] = pack2(chW2[(2*vp)*HH + u], chW2[(2*vp+1)*HH + u]);
    }
    if(tid < HH){ b1m[tid] = mhb1[tid]; b1c[tid] = chb1[tid]; }
    if(tid < MEAN_DIM) b2m[tid] = mhb2[tid];
    if(tid < COV_DIM)  b2c[tid] = chb2[tid];
    __syncthreads();

    int r0 = (blockIdx.x*256 + tid)*2;      // rows r0, r0+1
    const ulonglong2* opA = (const ulonglong2*)&g_dec[(size_t)r0*IN_DIM];
    ulonglong2 qa0 = opA[0], qa1 = opA[1], qa2 = opA[2], qa3 = opA[3];
    ulonglong2 qb0 = opA[4], qb1 = opA[5], qb2 = opA[6], qb3 = opA[7];
    ull ovA[8] = { qa0.x,qa0.y,qa1.x,qa1.y,qa2.x,qa2.y,qa3.x,qa3.y };
    ull ovB[8] = { qb0.x,qb0.y,qb1.x,qb1.y,qb2.x,qb2.y,qb3.x,qb3.y };

    ull amA[2], amB[2], acA[5], acB[5];
    amA[0] = amB[0] = pack2(b2m[0], b2m[1]);
    amA[1] = amB[1] = pack2(b2m[2], b2m[3]);
    #pragma unroll
    for(int vp = 0; vp < 5; vp++) acA[vp] = acB[vp] = pack2(b2c[2*vp], b2c[2*vp+1]);

    #pragma unroll 4
    for(int u = 0; u < HH; u++){
        const ull* w1mp = (const ull*)(w1m + u*16);
        const ull* w1cp = (const ull*)(w1c + u*16);
        ull a1A = 0, a1B = 0, a2A = 0, a2B = 0;
        #pragma unroll
        for(int i = 0; i < 8; i++){
            ull wm = w1mp[i], wc = w1cp[i];
            a1A = fma2(ovA[i], wm, a1A);
            a1B = fma2(ovB[i], wm, a1B);
            a2A = fma2(ovA[i], wc, a2A);
            a2B = fma2(ovB[i], wc, a2B);
        }
        float2 f;
        f = unpack2(a1A); float s1A = b1m[u] + f.x + f.y;
        f = unpack2(a1B); float s1B = b1m[u] + f.x + f.y;
        f = unpack2(a2A); float s2A = b1c[u] + f.x + f.y;
        f = unpack2(a2B); float s2B = b1c[u] + f.x + f.y;
        float g1A = gelu_exact(s1A), g1B = gelu_exact(s1B);
        float g2A = gelu_exact(s2A), g2B = gelu_exact(s2B);
        ull g1Ap = pack2(g1A, g1A), g1Bp = pack2(g1B, g1B);
        ull g2Ap = pack2(g2A, g2A), g2Bp = pack2(g2B, g2B);
        ull wm0 = w2mP[u*2], wm1 = w2mP[u*2+1];
        amA[0] = fma2(g1Ap, wm0, amA[0]); amA[1] = fma2(g1Ap, wm1, amA[1]);
        amB[0] = fma2(g1Bp, wm0, amB[0]); amB[1] = fma2(g1Bp, wm1, amB[1]);
        #pragma unroll
        for(int vp = 0; vp < 5; vp++){
            ull wcv = w2cP[u*5+vp];
            acA[vp] = fma2(g2Ap, wcv, acA[vp]);
            acB[vp] = fma2(g2Bp, wcv, acB[vp]);
        }
    }

    // clamp means dims 2,3 to [-1,1]
    { float2 m = unpack2(amA[1]);
      m.x = fminf(fmaxf(m.x, -1.f), 1.f); m.y = fminf(fmaxf(m.y, -1.f), 1.f);
      amA[1] = pack2(m.x, m.y); }
    { float2 m = unpack2(amB[1]);
      m.x = fminf(fmaxf(m.x, -1.f), 1.f); m.y = fminf(fmaxf(m.y, -1.f), 1.f);
      amB[1] = pack2(m.x, m.y); }

    ull* om = (ull*)(out + MEANS_OFF) + (size_t)r0*2;
    om[0] = amA[0]; om[1] = amA[1]; om[2] = amB[0]; om[3] = amB[1];
    ull* oc = (ull*)(out + COVS_OFF) + (size_t)r0*5;
    #pragma unroll
    for(int vp = 0; vp < 5; vp++){ oc[vp] = acA[vp]; oc[5+vp] = acB[vp]; }
}

// ---------------------------------------------------------------------------
extern "C" void kernel_launch(void* const* d_in, const int* in_sizes, int n_in,
                              void* d_out, int out_size)
{
    const float* x     = (const float*)d_in[0];
    const float* trg   = (const float*)d_in[1];
    const float* eWih  = (const float*)d_in[2];
    const float* ebih  = (const float*)d_in[3];
    const float* eWhh  = (const float*)d_in[4];
    const float* ebhh  = (const float*)d_in[5];
    const float* dWih  = (const float*)d_in[6];
    const float* dbih  = (const float*)d_in[7];
    const float* dWhh  = (const float*)d_in[8];
    const float* dbhh  = (const float*)d_in[9];
    const float* outW  = (const float*)d_in[10];
    const float* outb  = (const float*)d_in[11];
    const float* embW  = (const float*)d_in[12];
    const float* embb  = (const float*)d_in[13];
    const float* mhW1  = (const float*)d_in[14];
    const float* mhb1  = (const float*)d_in[15];
    const float* mhW2  = (const float*)d_in[16];
    const float* mhb2  = (const float*)d_in[17];
    const float* chW1  = (const float*)d_in[18];
    const float* chb1  = (const float*)d_in[19];
    const float* chW2  = (const float*)d_in[20];
    const float* chb2  = (const float*)d_in[21];

    cudaFuncSetAttribute(seq_kernel, cudaFuncAttributeMaxDynamicSharedMemorySize,
                         (int)sizeof(Smem));

    seq_kernel<<<GRID1, THREADS1, sizeof(Smem)>>>(
        x, trg, eWih, ebih, eWhh, ebhh, dWih, dbih, dWhh, dbhh,
        outW, outb, embW, embb);

    heads_kernel<<<(BB*SEQ_LEN)/512, 256>>>(
        mhW1, mhb1, mhW2, mhb2, chW1, chb1, chW2, chb2, (float*)d_out);
}